// round 9
// baseline (speedup 1.0000x reference)
#include <cuda_runtime.h>
#include <cuda_bf16.h>
#include <cstdint>
#include <cfloat>

// VectorQuantizer: x [N,256] fp32, emb [K,256] fp32.
// Out (fp32): quantized [N*256] | loss [1] | indices [N].
// bf16 mma prefilter (margin 2e-3) + fused exact rescore + epilogue.
// R9: 128x128 block tile, 64x32 warp tiles (halves LDSM bytes/MAC).

#define DIM   256
#define NMAX  65536
#define KMAX  4096
#define CAP   128
#define MG    2e-3f
#define BM    128
#define BN    128
#define NCH   (KMAX / BN)

__device__ __align__(16) float  g_S[NMAX];
__device__ __align__(16) float  g_c[KMAX];
__device__ unsigned int   g_cnt[NMAX];
__device__ unsigned long long g_cand[(size_t)NMAX * CAP];
__device__ __align__(16) __nv_bfloat16 g_xb[(size_t)NMAX * DIM];
__device__ __align__(16) __nv_bfloat16 g_eb[(size_t)KMAX * DIM];
__device__ double         g_acc;

// ---------------------------------------------------------------------------
__global__ __launch_bounds__(256) void k_prep_x(const float* __restrict__ x, int N) {
    int n = blockIdx.x * blockDim.x + threadIdx.x;
    if (n >= N) return;
    g_cnt[n] = 0u;
    const float4* xr = (const float4*)(x + (size_t)n * DIM);
    __nv_bfloat162* dst = (__nv_bfloat162*)(g_xb + (size_t)n * DIM);
    float s = 0.0f;
    #pragma unroll 8
    for (int i = 0; i < 64; i++) {
        float4 v = __ldg(xr + i);
        s = __fadd_rn(s, __fmul_rn(v.x, v.x));
        s = __fadd_rn(s, __fmul_rn(v.y, v.y));
        s = __fadd_rn(s, __fmul_rn(v.z, v.z));
        s = __fadd_rn(s, __fmul_rn(v.w, v.w));
        dst[2 * i + 0] = __floats2bfloat162_rn(v.x, v.y);
        dst[2 * i + 1] = __floats2bfloat162_rn(v.z, v.w);
    }
    g_S[n] = s;
}

__global__ __launch_bounds__(256) void k_prep_e(const float* __restrict__ emb, int K) {
    int k = blockIdx.x * blockDim.x + threadIdx.x;
    if (k == 0) g_acc = 0.0;
    if (k >= K) return;
    const float4* er = (const float4*)(emb + (size_t)k * DIM);
    __nv_bfloat162* dst = (__nv_bfloat162*)(g_eb + (size_t)k * DIM);
    float s = 0.0f;
    #pragma unroll 8
    for (int i = 0; i < 64; i++) {
        float4 v = __ldg(er + i);
        s = __fadd_rn(s, __fmul_rn(v.x, v.x));
        s = __fadd_rn(s, __fmul_rn(v.y, v.y));
        s = __fadd_rn(s, __fmul_rn(v.z, v.z));
        s = __fadd_rn(s, __fmul_rn(v.w, v.w));
        dst[2 * i + 0] = __floats2bfloat162_rn(v.x, v.y);
        dst[2 * i + 1] = __floats2bfloat162_rn(v.z, v.w);
    }
    g_c[k] = s;
}

// ---------------------------------------------------------------------------
__device__ __forceinline__ void cpa16(uint32_t s, const void* g) {
    asm volatile("cp.async.cg.shared.global [%0], [%1], 16;\n" :: "r"(s), "l"(g));
}
__device__ __forceinline__ void ldsm4(uint32_t* r, uint32_t a) {
    asm volatile("ldmatrix.sync.aligned.m8n8.x4.shared.b16 {%0,%1,%2,%3}, [%4];"
        : "=r"(r[0]), "=r"(r[1]), "=r"(r[2]), "=r"(r[3]) : "r"(a));
}
__device__ __forceinline__ void mma16816(float* d, const uint32_t* a,
                                         uint32_t b0, uint32_t b1) {
    asm volatile("mma.sync.aligned.m16n8k16.row.col.f32.bf16.bf16.f32 "
        "{%0,%1,%2,%3}, {%4,%5,%6,%7}, {%8,%9}, {%0,%1,%2,%3};"
        : "+f"(d[0]), "+f"(d[1]), "+f"(d[2]), "+f"(d[3])
        : "r"(a[0]), "r"(a[1]), "r"(a[2]), "r"(a[3]), "r"(b0), "r"(b1));
}

// bf16 tile: row r = 512B (256 dims), 32 units of 16B, low-3-bit XOR swizzle
__device__ __forceinline__ uint32_t xoff(int r, int j) {
    return (uint32_t)((r << 9) + (((j & 24) | ((j ^ r) & 7)) << 4));
}

// smem map (bytes)
#define SM_XS  0                        // 128*512 = 65536
#define SM_ES  65536                    // 2 * 65536
#define SM_SC  (SM_ES + 2 * 65536)      // 2 * 512B c chunks
#define SM_SS  (SM_SC + 1024)           // 128 * 4
#define SM_RM  (SM_SS + 512)            // 128 * 4
#define SM_SI  (SM_RM + 512)            // 128 * 4
#define SM_DR  (SM_SI + 512)            // 8 doubles
#define SM_TOT (SM_DR + 64)

__device__ __forceinline__ unsigned long long exact_pack(
        const float* xr, const float* emb, float Sv, unsigned int k) {
    const float* er = emb + (size_t)k * DIM;
    float m = 0.0f;
    #pragma unroll 4
    for (int i = 0; i < 64; i++) {
        float4 xv = __ldg((const float4*)xr + i);
        float4 ev = __ldg((const float4*)er + i);
        m = __fmaf_rn(xv.x, ev.x, m);
        m = __fmaf_rn(xv.y, ev.y, m);
        m = __fmaf_rn(xv.z, ev.z, m);
        m = __fmaf_rn(xv.w, ev.w, m);
    }
    float d = __fadd_rn(__fmaf_rn(-2.0f, m, Sv), g_c[k]);
    return ((unsigned long long)__float_as_uint(d) << 32) | k;
}

__global__ __launch_bounds__(256, 1) void k_gemm(const float* __restrict__ x,
                                                 const float* __restrict__ emb,
                                                 float* __restrict__ out,
                                                 float* __restrict__ outIdx,
                                                 int N, int K) {
    extern __shared__ char smem[];
    const uint32_t sb = (uint32_t)__cvta_generic_to_shared(smem);
    float*  sS   = (float*)(smem + SM_SS);
    int*    srm  = (int*)  (smem + SM_RM);
    int*    sidx = (int*)  (smem + SM_SI);
    double* sred = (double*)(smem + SM_DR);

    const int tid  = threadIdx.x;
    const int lane = tid & 31, wid = tid >> 5;
    const int rb   = blockIdx.x * BM;

    if (tid < BM) { srm[tid] = 0x7f7fffff; sS[tid] = g_S[rb + tid]; }

    // preload x tile + e chunk 0 + c chunk 0
    for (int i = tid; i < BM * 32; i += 256) {
        int r = i >> 5, j = i & 31;
        cpa16(sb + SM_XS + xoff(r, j), g_xb + (size_t)(rb + r) * DIM + j * 8);
        cpa16(sb + SM_ES + xoff(r, j), g_eb + (size_t)r * DIM + j * 8);
    }
    if (tid < 32) cpa16(sb + SM_SC + tid * 16, g_c + tid * 4);
    asm volatile("cp.async.commit_group;\n");

    const int mi = wid >> 2;       // 0..1 : 64-row half
    const int ni = wid & 3;        // 0..3 : 32-col group
    const int g  = lane >> 2, t = lane & 3;

    for (int ci = 0; ci < NCH; ci++) {
        const int buf = ci & 1;
        asm volatile("cp.async.wait_group 0;\n");
        __syncthreads();

        if (ci + 1 < NCH) {
            const int nb = (ci + 1) & 1;
            for (int i = tid; i < BN * 32; i += 256) {
                int r = i >> 5, j = i & 31;
                cpa16(sb + SM_ES + nb * 65536 + xoff(r, j),
                      g_eb + (size_t)((ci + 1) * BN + r) * DIM + j * 8);
            }
            if (tid < 32) cpa16(sb + SM_SC + nb * 512 + tid * 16,
                                g_c + (ci + 1) * BN + tid * 4);
            asm volatile("cp.async.commit_group;\n");
        }

        float acc[4][4][4];           // [mt 16-row][nn 8-col][quad]
        #pragma unroll
        for (int mt = 0; mt < 4; mt++)
            #pragma unroll
            for (int nn = 0; nn < 4; nn++)
                #pragma unroll
                for (int q = 0; q < 4; q++) acc[mt][nn][q] = 0.0f;

        const uint32_t esb = sb + SM_ES + buf * 65536;
        #pragma unroll
        for (int ks = 0; ks < 16; ks++) {
            uint32_t a[4][4], b[2][4];
            #pragma unroll
            for (int mt = 0; mt < 4; mt++) {
                int r = mi * 64 + mt * 16 + (lane & 7) + ((lane >> 3) & 1) * 8;
                ldsm4(a[mt], sb + SM_XS + xoff(r, ks * 2 + (lane >> 4)));
            }
            #pragma unroll
            for (int nb2 = 0; nb2 < 2; nb2++) {
                int r = ni * 32 + nb2 * 16 + (lane & 7) + (lane >> 4) * 8;
                ldsm4(b[nb2], esb + xoff(r, ks * 2 + ((lane >> 3) & 1)));
            }
            #pragma unroll
            for (int mt = 0; mt < 4; mt++)
                #pragma unroll
                for (int nb2 = 0; nb2 < 2; nb2++) {
                    mma16816(acc[mt][nb2 * 2 + 0], a[mt], b[nb2][0], b[nb2][1]);
                    mma16816(acc[mt][nb2 * 2 + 1], a[mt], b[nb2][2], b[nb2][3]);
                }
        }

        // distances in place
        const float* scb = (const float*)(smem + SM_SC + buf * 512);
        #pragma unroll
        for (int mt = 0; mt < 4; mt++)
            #pragma unroll
            for (int nn = 0; nn < 4; nn++)
                #pragma unroll
                for (int h = 0; h < 2; h++)
                    #pragma unroll
                    for (int q = 0; q < 2; q++) {
                        const int rl = mi * 64 + mt * 16 + g + h * 8;
                        const int cl = ni * 32 + ((nn >> 1) << 4) + ((nn & 1) << 3)
                                     + 2 * t + q;
                        acc[mt][nn][h * 2 + q] = __fadd_rn(
                            __fmaf_rn(-2.0f, acc[mt][nn][h * 2 + q], sS[rl]),
                            scb[cl]);
                    }

        if (ci == 0) {
            // two-phase for the first chunk (running min not yet seeded)
            #pragma unroll
            for (int mt = 0; mt < 4; mt++)
                #pragma unroll
                for (int h = 0; h < 2; h++) {
                    const int rl = mi * 64 + mt * 16 + g + h * 8;
                    float lmin = FLT_MAX;
                    #pragma unroll
                    for (int nn = 0; nn < 4; nn++)
                        #pragma unroll
                        for (int q = 0; q < 2; q++)
                            lmin = fminf(lmin, acc[mt][nn][h * 2 + q]);
                    lmin = fminf(lmin, __shfl_xor_sync(0xffffffffu, lmin, 1));
                    lmin = fminf(lmin, __shfl_xor_sync(0xffffffffu, lmin, 2));
                    if (t == 0) atomicMin(&srm[rl], __float_as_int(lmin));
                }
            __syncthreads();
        }
        // appends vs (possibly stale) running min — superset-safe
        const int cb = ci * BN + ni * 32;
        #pragma unroll
        for (int mt = 0; mt < 4; mt++)
            #pragma unroll
            for (int h = 0; h < 2; h++) {
                const int rl  = mi * 64 + mt * 16 + g + h * 8;
                const float rmw = __int_as_float(srm[rl]) + MG;
                float lmin = FLT_MAX;
                #pragma unroll
                for (int nn = 0; nn < 4; nn++)
                    #pragma unroll
                    for (int q = 0; q < 2; q++) {
                        float dist = acc[mt][nn][h * 2 + q];
                        lmin = fminf(lmin, dist);
                        if (dist <= rmw) {
                            unsigned int pos = atomicAdd(&g_cnt[rb + rl], 1u);
                            if (pos < CAP)
                                g_cand[(size_t)(rb + rl) * CAP + pos] =
                                    ((unsigned long long)__float_as_uint(dist) << 32)
                                    | (unsigned int)(cb + ((nn >> 1) << 4)
                                                     + ((nn & 1) << 3) + 2 * t + q);
                        }
                    }
                if (ci > 0) {
                    lmin = fminf(lmin, __shfl_xor_sync(0xffffffffu, lmin, 1));
                    lmin = fminf(lmin, __shfl_xor_sync(0xffffffffu, lmin, 2));
                    if (t == 0) atomicMin(&srm[rl], __float_as_int(lmin));
                }
            }
    }
    __syncthreads();

    // ---- fused tail 1: exact rescore (one warp per row, 16 rows/warp) ----
    for (int rr = wid; rr < BM; rr += 8) {
        const int n = rb + rr;
        const unsigned int cnt = g_cnt[n];
        const float Sv  = sS[rr];
        const float thr = __int_as_float(srm[rr]) + MG;
        const float* xr = x + (size_t)n * DIM;
        unsigned long long best = 0xffffffffffffffffULL;
        if (cnt <= CAP) {
            for (unsigned int e = lane; e < cnt; e += 32) {
                unsigned long long ent = g_cand[(size_t)n * CAP + e];
                float dt = __uint_as_float((unsigned int)(ent >> 32));
                if (dt > thr) continue;
                unsigned long long v =
                    exact_pack(xr, emb, Sv, (unsigned int)(ent & 0xffffffffu));
                if (v < best) best = v;
            }
        } else {
            for (int k = lane; k < K; k += 32) {
                unsigned long long v = exact_pack(xr, emb, Sv, (unsigned int)k);
                if (v < best) best = v;
            }
        }
        #pragma unroll
        for (int o = 16; o; o >>= 1) {
            unsigned long long v = __shfl_xor_sync(0xffffffffu, best, o);
            if (v < best) best = v;
        }
        if (lane == 0) sidx[rr] = (int)(best & 0xffffffffu);
    }
    __syncthreads();

    // ---- fused tail 2: quantized output + loss partial + indices ----
    double ls = 0.0;
    for (int rr = wid; rr < BM; rr += 8) {
        const int n = rb + rr;
        const int idx = sidx[rr];
        if (lane == 0 && outIdx != nullptr) outIdx[n] = (float)idx;
        const float4* xv4 = (const float4*)(x + (size_t)n * DIM);
        const float4* ev4 = (const float4*)(emb + (size_t)idx * DIM);
        float4* ov4 = (float4*)(out + (size_t)n * DIM);
        for (int i = lane; i < 64; i += 32) {
            float4 xv = __ldg(xv4 + i);
            float4 ev = __ldg(ev4 + i);
            float d0 = __fsub_rn(ev.x, xv.x), d1 = __fsub_rn(ev.y, xv.y);
            float d2 = __fsub_rn(ev.z, xv.z), d3 = __fsub_rn(ev.w, xv.w);
            float4 o;
            o.x = __fadd_rn(xv.x, d0); o.y = __fadd_rn(xv.y, d1);
            o.z = __fadd_rn(xv.z, d2); o.w = __fadd_rn(xv.w, d3);
            ov4[i] = o;
            ls += (double)__fmul_rn(d0, d0) + (double)__fmul_rn(d1, d1)
                + (double)__fmul_rn(d2, d2) + (double)__fmul_rn(d3, d3);
        }
    }
    #pragma unroll
    for (int o = 16; o; o >>= 1) ls += __shfl_xor_sync(0xffffffffu, ls, o);
    if (lane == 0) sred[wid] = ls;
    __syncthreads();
    if (tid == 0) {
        double s = 0.0;
        #pragma unroll
        for (int w = 0; w < 8; w++) s += sred[w];
        atomicAdd(&g_acc, s);
    }
}

__global__ void k_fin(float* __restrict__ out, int N) {
    double m = g_acc / ((double)N * (double)DIM);
    float L = (float)m;
    out[(size_t)N * DIM] = __fadd_rn(L, __fmul_rn(0.25f, L));
}

// ---------------------------------------------------------------------------
extern "C" void kernel_launch(void* const* d_in, const int* in_sizes, int n_in,
                              void* d_out, int out_size) {
    const float* x   = (const float*)d_in[0];
    const float* emb = (const float*)d_in[1];
    const int N = in_sizes[0] / DIM;
    const int K = in_sizes[1] / DIM;
    float* out = (float*)d_out;

    const long long Nq = (long long)N * DIM;
    const bool has_loss = (long long)out_size > Nq;
    const bool has_idx  = (long long)out_size >= Nq + 1 + N;
    float* outIdx = has_idx ? out + Nq + 1 : nullptr;

    cudaFuncSetAttribute(k_gemm, cudaFuncAttributeMaxDynamicSharedMemorySize,
                         SM_TOT);

    k_prep_e<<<(K + 255) / 256, 256>>>(emb, K);
    k_prep_x<<<(N + 255) / 256, 256>>>(x, N);
    k_gemm<<<N / BM, 256, SM_TOT>>>(x, emb, out, outIdx, N, K);
    if (has_loss) k_fin<<<1, 1>>>(out, N);
}